// round 6
// baseline (speedup 1.0000x reference)
#include <cuda_runtime.h>
#include <cuda_fp16.h>

#define NN 50000
#define FF 16
#define EE 800000
#define HH 64
#define TOUT 10
#define NF (NN*FF)
#define NBIN 1024
#define SBLK 296
#define STHR 512
#define SWARPS (SBLK*(STHR/32))   // 4736 warps

// ---------------- device state ----------------
__device__ float   g_x0[NF];
__device__ float   g_xi[NF];
__device__ float   g_k[6][NF];
__device__ __half2 g_uv[2][NN*32];   // packed u: (.x=ch lane, .y=ch lane+32), double-buffered
__device__ float   g_v[NN*HH];
__device__ float   g_augproj[NN*HH];
__device__ float   g_ys[TOUT*NF];
__device__ int     g_deg[NN];
__device__ int     g_rowptr[NN+1];
__device__ int     g_wptr[NN];
__device__ int     g_src_sorted[EE];
__device__ float4  g_ea_sorted[EE];
__device__ int     g_dbin[NBIN];
__device__ int     g_dwptr[NBIN];
__device__ int     g_nodes_sorted[NN];

// DOPRI5 coefficients. Row 0 unused, rows 1..5 = A[0..4], row 6 = B.
__constant__ float c_coef[7][6] = {
  {0.f,0.f,0.f,0.f,0.f,0.f},
  {(float)(0.2), 0.f,0.f,0.f,0.f,0.f},
  {(float)(3.0/40.0), (float)(9.0/40.0), 0.f,0.f,0.f,0.f},
  {(float)(44.0/45.0), (float)(-56.0/15.0), (float)(32.0/9.0), 0.f,0.f,0.f},
  {(float)(19372.0/6561.0), (float)(-25360.0/2187.0), (float)(64448.0/6561.0), (float)(-212.0/729.0), 0.f,0.f},
  {(float)(9017.0/3168.0), (float)(-355.0/33.0), (float)(46732.0/5247.0), (float)(49.0/176.0), (float)(-5103.0/18656.0), 0.f},
  {(float)(35.0/384.0), 0.f, (float)(500.0/1113.0), (float)(125.0/192.0), (float)(-2187.0/6784.0), (float)(11.0/84.0)}
};
__constant__ float c_C[6] = {0.f, 0.2f, 0.3f, 0.8f, (float)(8.0/9.0), 1.f};

__device__ __forceinline__ float tanha(float x) {
  float r;
  asm("tanh.approx.f32 %0, %1;" : "=f"(r) : "f"(x));
  return r;
}

// ---------------- setup kernels (exactly 5 launches before stage loop) ----------------

// launch 0: initial state + zeroing of histograms
__global__ __launch_bounds__(256) void init_kernel(
    const float* __restrict__ xh,
    const float* __restrict__ W1m, const float* __restrict__ b1m)
{
  __shared__ float sW[32 * 64];
  __shared__ float sb[64];
  __shared__ float sxi[8][16];
  int tid = threadIdx.x;
  int gid = blockIdx.x * 256 + tid;
  if (gid < NN) g_deg[gid] = 0;
  if (gid < NBIN) g_dbin[gid] = 0;
  #pragma unroll
  for (int i = tid; i < 512; i += 256) ((float4*)sW)[i] = ((const float4*)W1m)[i];
  if (tid < 16) ((float4*)sb)[tid] = ((const float4*)b1m)[tid];
  int w = tid >> 5, lane = tid & 31;
  int n = blockIdx.x * 8 + w;
  if (n < NN) {
    if (lane < 16) {
      int idx = n * 16 + lane;
      float xv = xh[9 * NF + idx];
      g_x0[idx] = xv;
      g_xi[idx] = xv;
      sxi[w][lane] = xv;
    }
  }
  __syncthreads();
  if (n >= NN) return;
  float u0 = 0.f, u1 = 0.f;
  float v0 = sb[lane], v1 = sb[32 + lane];
  #pragma unroll
  for (int i = 0; i < 16; i++) {
    float xv = sxi[w][i];
    u0 += xv * sW[i * 64 + lane];
    u1 += xv * sW[i * 64 + 32 + lane];
    v0 += xv * sW[(16 + i) * 64 + lane];
    v1 += xv * sW[(16 + i) * 64 + 32 + lane];
  }
  g_uv[0][n * 32 + lane] = __floats2half2_rn(u0, u1);
  g_v[n * 64 + lane] = v0;
  g_v[n * 64 + 32 + lane] = v1;
}

// launch 1: aug features projected through W1n rows [32,208) with b1n folded in
__global__ __launch_bounds__(256) void augproj_kernel(
    const float* __restrict__ xh, const float* __restrict__ xm,
    const float* __restrict__ W1n, const float* __restrict__ b1n)
{
  __shared__ float saug[4][176];
  int tid = threadIdx.x;
  int ln = tid >> 6;
  int ch = tid & 63;
  int n = blockIdx.x * 4 + ln;
  if (ch < 16) {
    int f = ch;
    float xs[10], ms[10];
    float sm = 0.f, cm = 0.f;
    #pragma unroll
    for (int tt = 0; tt < 10; tt++) {
      xs[tt] = xh[(tt * NN + n) * FF + f];
      ms[tt] = xm[tt * NN + n];
      sm += xs[tt] * ms[tt];
      cm += ms[tt];
    }
    float cnt = fmaxf(cm, 1.0f);
    float mean = sm / cnt;
    float var = 0.f;
    #pragma unroll
    for (int tt = 0; tt < 10; tt++) { float d = xs[tt] - mean; var += d * d * ms[tt]; }
    var /= cnt;
    #pragma unroll
    for (int tt = 0; tt < 9; tt++)
      saug[ln][tt * 16 + f] = (xs[tt + 1] - xs[tt]) * (ms[tt + 1] * ms[tt]);
    saug[ln][144 + f] = mean;
    saug[ln][160 + f] = var;
  }
  __syncthreads();
  float acc = b1n[ch];
  #pragma unroll 8
  for (int r = 0; r < 176; r++)
    acc += saug[ln][r] * W1n[(32 + r) * 64 + ch];
  g_augproj[n * 64 + ch] = acc;
}

// launch 2: degree histogram
__global__ __launch_bounds__(256) void hist_kernel(const int* __restrict__ ei) {
  int e = blockIdx.x * 256 + threadIdx.x;
  if (e < EE) atomicAdd(&g_deg[ei[EE + e]], 1);
}

// launch 3: rowptr scan + degree-bin count + bin scan (single block)
__global__ __launch_bounds__(1024) void scan_kernel() {
  __shared__ int wsum[32];
  int tid = threadIdx.x, lane = tid & 31, wid = tid >> 5;
  int carry = 0;
  for (int base = 0; base < NN; base += 1024) {
    int i = base + tid;
    int v = (i < NN) ? g_deg[i] : 0;
    int x = v;
    #pragma unroll
    for (int o = 1; o < 32; o <<= 1) { int y = __shfl_up_sync(0xffffffffu, x, o); if (lane >= o) x += y; }
    if (lane == 31) wsum[wid] = x;
    __syncthreads();
    if (wid == 0) {
      int s = wsum[lane];
      #pragma unroll
      for (int o = 1; o < 32; o <<= 1) { int y = __shfl_up_sync(0xffffffffu, s, o); if (lane >= o) s += y; }
      wsum[lane] = s;
    }
    __syncthreads();
    int incl = x + carry + (wid > 0 ? wsum[wid - 1] : 0);
    if (i < NN) { g_rowptr[i + 1] = incl; g_wptr[i] = incl - v; }
    carry += wsum[31];
    __syncthreads();
  }
  if (tid == 0) g_rowptr[0] = 0;
  __syncthreads();
  // degree bins (descending order)
  for (int n = tid; n < NN; n += 1024) {
    int d = g_deg[n]; if (d > NBIN - 1) d = NBIN - 1;
    atomicAdd(&g_dbin[(NBIN - 1) - d], 1);
  }
  __syncthreads();
  // bin exclusive scan
  {
    int v = __ldcg(&g_dbin[tid]);
    int x = v;
    #pragma unroll
    for (int o = 1; o < 32; o <<= 1) { int y = __shfl_up_sync(0xffffffffu, x, o); if (lane >= o) x += y; }
    if (lane == 31) wsum[wid] = x;
    __syncthreads();
    if (wid == 0) {
      int s = wsum[lane];
      #pragma unroll
      for (int o = 1; o < 32; o <<= 1) { int y = __shfl_up_sync(0xffffffffu, s, o); if (lane >= o) s += y; }
      wsum[lane] = s;
    }
    __syncthreads();
    int incl = x + (wid > 0 ? wsum[wid - 1] : 0);
    g_dwptr[tid] = incl - v;
  }
}

// launch 4: edge scatter into CSR + node scatter into degree-sorted order
__global__ __launch_bounds__(256) void scatter_kernel(
    const int* __restrict__ ei, const float* __restrict__ ea)
{
  int e = blockIdx.x * 256 + threadIdx.x;
  if (e < EE) {
    int d = ei[EE + e];
    int pos = atomicAdd(&g_wptr[d], 1);
    g_src_sorted[pos] = ei[e];
    g_ea_sorted[pos] = ((const float4*)ea)[e];
  }
  if (e < NN) {
    int dd = g_deg[e]; if (dd > NBIN - 1) dd = NBIN - 1;
    int pos = atomicAdd(&g_dwptr[(NBIN - 1) - dd], 1);
    g_nodes_sorted[pos] = e;
  }
}

// ---------------- fused per-stage kernel (templated on stage S) ----------------
template<int S>
__global__ __launch_bounds__(STHR) void stage_kernel(
    int it, int sub, int outrow, int pb,
    const float* __restrict__ t,
    const float* __restrict__ W1m, const float* __restrict__ W2m,
    const float* __restrict__ b2m, const float* __restrict__ W1n,
    const float* __restrict__ W2n, const float* __restrict__ b2n,
    const float* __restrict__ b1m)
{
  __shared__ float  sWea[4 * 64];
  __shared__ float  sW2mT[16 * 64];   // [j][c]
  __shared__ float  sW2nT[16 * 64];   // [j][c]
  __shared__ float2 sW1nxP[16 * 32];  // [i][l] = (W1n[i][l], W1n[i][l+32])
  __shared__ float2 sW1naP[16 * 32];
  __shared__ float2 sW1mUP[16 * 32];  // W1m rows 0..15
  __shared__ float2 sW1mVP[16 * 32];  // W1m rows 16..31
  __shared__ float  swt[64];
  __shared__ float  sb1m[64];
  __shared__ float  sb2m[16], sb2n[16];
  __shared__ float  sbuf[STHR/32][64];
  __shared__ float  sxi[STHR/32][16];
  __shared__ float  sagg[STHR/32][16];
  __shared__ float  sxin[STHR/32][16];

  int tid = threadIdx.x;
  if (tid < 64) ((float4*)sWea)[tid] = ((const float4*)(W1m + 32 * 64))[tid];
  for (int i = tid; i < 1024; i += STHR) {
    int c = i & 63, j = i >> 6;
    sW2mT[i] = W2m[c * 16 + j];
    sW2nT[i] = W2n[c * 16 + j];
  }
  for (int i = tid; i < 512; i += STHR) {
    int r = i >> 5, l = i & 31;
    sW1nxP[i] = make_float2(W1n[r * 64 + l],          W1n[r * 64 + 32 + l]);
    sW1naP[i] = make_float2(W1n[1024 + r * 64 + l],   W1n[1024 + r * 64 + 32 + l]);
    sW1mUP[i] = make_float2(W1m[r * 64 + l],          W1m[r * 64 + 32 + l]);
    sW1mVP[i] = make_float2(W1m[(16 + r) * 64 + l],   W1m[(16 + r) * 64 + 32 + l]);
  }
  if (tid < 16) ((float4*)swt)[tid] = ((const float4*)(W1n + 208 * 64))[tid];
  if (tid >= 16 && tid < 32) ((float4*)sb1m)[tid - 16] = ((const float4*)b1m)[tid - 16];
  if (tid >= 32 && tid < 36) ((float4*)sb2m)[tid - 32] = ((const float4*)b2m)[tid - 32];
  if (tid >= 36 && tid < 40) ((float4*)sb2n)[tid - 36] = ((const float4*)b2n)[tid - 36];
  __syncthreads();

  int w = tid >> 5, lane = tid & 31;
  int gw = blockIdx.x * (STHR / 32) + w;
  int j = lane & 15;
  int cbase = (lane < 16) ? 0 : 32;

  float tA = __ldg(t + it), tB = __ldg(t + it + 1);
  float dti = (tB - tA) * 0.25f;
  float ti = tA + (float)sub * dti + c_C[S] * dti;
  constexpr int krow = (S < 5) ? S + 1 : 6;

  // edge-layer weights in registers
  float wx0 = sWea[lane],        wx1 = sWea[32 + lane];
  float wy0 = sWea[64 + lane],   wy1 = sWea[96 + lane];
  float wz0 = sWea[128 + lane],  wz1 = sWea[160 + lane];
  float ww0 = sWea[192 + lane],  ww1 = sWea[224 + lane];

  const unsigned* __restrict__ U = (const unsigned*)&g_uv[pb][0];

  for (int ni = gw; ni < NN; ni += SWARPS) {
    int n = g_nodes_sorted[ni];

    if (lane < 16) sxi[w][lane] = g_xi[n * 16 + lane];
    __syncwarp();

    float v0 = g_v[n * 64 + lane];
    float v1 = g_v[n * 64 + 32 + lane];

    float acc0 = 0.f, acc1 = 0.f;
    int beg = g_rowptr[n], end = g_rowptr[n + 1];

    // 3-slot software pipeline (prefetch depth 2); cached loads (L1 valid within launch)
    float4 eaA = make_float4(0.f,0.f,0.f,0.f), eaB = eaA;
    unsigned uhA = 0u, uhB = 0u;
    if (beg < end) {
      int s0 = __ldg(g_src_sorted + beg);
      eaA = __ldg(g_ea_sorted + beg);
      uhA = __ldg(U + s0 * 32 + lane);
    }
    if (beg + 1 < end) {
      int s1 = __ldg(g_src_sorted + beg + 1);
      eaB = __ldg(g_ea_sorted + beg + 1);
      uhB = __ldg(U + s1 * 32 + lane);
    }
    for (int e = beg; e < end; e++) {
      float4 ea = eaA; unsigned uh = uhA;
      eaA = eaB; uhA = uhB;
      if (e + 2 < end) {
        int sn = __ldg(g_src_sorted + e + 2);
        eaB = __ldg(g_ea_sorted + e + 2);
        uhB = __ldg(U + sn * 32 + lane);
      }
      __half2 h2 = *reinterpret_cast<__half2*>(&uh);
      float2 uf = __half22float2(h2);
      float a0 = uf.x + v0;
      float a1 = uf.y + v1;
      a0 += ea.x * wx0 + ea.y * wy0 + ea.z * wz0 + ea.w * ww0;
      a1 += ea.x * wx1 + ea.y * wy1 + ea.z * wz1 + ea.w * ww1;
      acc0 += tanha(a0);
      acc1 += tanha(a1);
    }

    // agg16 = hsum @ W2m + deg*b2m   (vectorized LDS.128 both operands)
    sbuf[w][lane] = acc0;
    sbuf[w][32 + lane] = acc1;
    __syncwarp();
    float p = 0.f;
    {
      const float4* hb = (const float4*)&sbuf[w][cbase];
      const float4* wb = (const float4*)&sW2mT[j * 64 + cbase];
      #pragma unroll
      for (int c4 = 0; c4 < 8; c4++) {
        float4 hv = hb[c4], wv = wb[c4];
        p += hv.x * wv.x + hv.y * wv.y + hv.z * wv.z + hv.w * wv.w;
      }
    }
    p += __shfl_xor_sync(0xffffffffu, p, 16);
    float degf = (float)(end - beg);
    if (lane < 16) sagg[w][lane] = p + degf * sb2m[j];
    __syncwarp();

    // hidden = xi@W1n_x + agg@W1n_agg + aug_proj + ti*wt
    float h0 = g_augproj[n * 64 + lane]      + ti * swt[lane];
    float h1 = g_augproj[n * 64 + 32 + lane] + ti * swt[32 + lane];
    #pragma unroll
    for (int i4 = 0; i4 < 4; i4++) {
      float4 xv4 = ((const float4*)sxi[w])[i4];
      float4 av4 = ((const float4*)sagg[w])[i4];
      #pragma unroll
      for (int k = 0; k < 4; k++) {
        int i = i4 * 4 + k;
        float xv = (k == 0) ? xv4.x : (k == 1) ? xv4.y : (k == 2) ? xv4.z : xv4.w;
        float av = (k == 0) ? av4.x : (k == 1) ? av4.y : (k == 2) ? av4.z : av4.w;
        float2 wx = sW1nxP[i * 32 + lane];
        float2 wa = sW1naP[i * 32 + lane];
        h0 += xv * wx.x + av * wa.x;
        h1 += xv * wx.y + av * wa.y;
      }
    }
    __syncwarp();
    sbuf[w][lane] = tanha(h0);
    sbuf[w][32 + lane] = tanha(h1);
    __syncwarp();

    float o = 0.f;
    {
      const float4* hb = (const float4*)&sbuf[w][cbase];
      const float4* wb = (const float4*)&sW2nT[j * 64 + cbase];
      #pragma unroll
      for (int c4 = 0; c4 < 8; c4++) {
        float4 hv = hb[c4], wv = wb[c4];
        o += hv.x * wv.x + hv.y * wv.y + hv.z * wv.z + hv.w * wv.w;
      }
    }
    o += __shfl_xor_sync(0xffffffffu, o, 16);
    float kval = o + sb2n[j];

    // epilogue: k store, xi_{S+1} combine, u/v projection into buffer pb^1
    if (lane < 16) {
      int idx = n * 16 + j;
      g_k[S][idx] = kval;
      float acc = c_coef[krow][S] * kval;
      #pragma unroll
      for (int jj = 0; jj < S; jj++) acc += c_coef[krow][jj] * g_k[jj][idx];
      float xv = g_x0[idx] + dti * acc;
      if (S == 5) {
        g_x0[idx] = xv;
        if (outrow >= 0) g_ys[outrow * NF + idx] = xv;
      }
      g_xi[idx] = xv;
      sxin[w][j] = xv;
    }
    __syncwarp();

    float u0 = 0.f, u1 = 0.f;
    float nv0 = sb1m[lane], nv1 = sb1m[32 + lane];
    #pragma unroll
    for (int i4 = 0; i4 < 4; i4++) {
      float4 xv4 = ((const float4*)sxin[w])[i4];
      #pragma unroll
      for (int k = 0; k < 4; k++) {
        int i = i4 * 4 + k;
        float xv = (k == 0) ? xv4.x : (k == 1) ? xv4.y : (k == 2) ? xv4.z : xv4.w;
        float2 wu = sW1mUP[i * 32 + lane];
        float2 wv = sW1mVP[i * 32 + lane];
        u0  += xv * wu.x;  u1  += xv * wu.y;
        nv0 += xv * wv.x;  nv1 += xv * wv.y;
      }
    }
    g_uv[pb ^ 1][n * 32 + lane] = __floats2half2_rn(u0, u1);
    g_v[n * 64 + lane] = nv0;
    g_v[n * 64 + 32 + lane] = nv1;
  }
}

__global__ __launch_bounds__(256) void gather_out_kernel(
    const int* __restrict__ mask_idx, float* __restrict__ out)
{
  int idx = blockIdx.x * 256 + threadIdx.x;
  if (idx < TOUT * NF) {
    int row = idx / NF;
    int rem = idx - row * NF;
    out[idx] = g_ys[mask_idx[row] * NF + rem];
  }
}

// ---------------- launcher ----------------
extern "C" void kernel_launch(void* const* d_in, const int* in_sizes, int n_in,
                              void* d_out, int out_size)
{
  const float* x_hist   = (const float*)d_in[0];
  const float* x_mask   = (const float*)d_in[1];
  const int*   ei       = (const int*)d_in[2];
  const float* ea       = (const float*)d_in[3];
  const float* t        = (const float*)d_in[4];
  const int*   mask_idx = (const int*)d_in[5];
  const float* W1m = (const float*)d_in[6];
  const float* b1m = (const float*)d_in[7];
  const float* W2m = (const float*)d_in[8];
  const float* b2m = (const float*)d_in[9];
  const float* W1n = (const float*)d_in[10];
  const float* b1n = (const float*)d_in[11];
  const float* W2n = (const float*)d_in[12];
  const float* b2n = (const float*)d_in[13];
  float* out = (float*)d_out;

  // exactly 5 setup launches so ncu (-s 5 -c 1) captures the first stage kernel
  init_kernel<<<(NN + 7) / 8, 256>>>(x_hist, W1m, b1m);                 // 0
  augproj_kernel<<<NN / 4, 256>>>(x_hist, x_mask, W1n, b1n);            // 1
  hist_kernel<<<(EE + 255) / 256, 256>>>(ei);                           // 2
  scan_kernel<<<1, 1024>>>();                                           // 3
  scatter_kernel<<<(EE + 255) / 256, 256>>>(ei, ea);                    // 4

  int L = 0;
  for (int it = 0; it < TOUT; it++) {
    for (int sub = 0; sub < 4; sub++) {
      for (int s = 0; s < 6; s++) {
        int outrow = (s == 5 && sub == 3) ? it : -1;
        int pb = L & 1;
        switch (s) {
          case 0: stage_kernel<0><<<SBLK, STHR>>>(it, sub, outrow, pb, t, W1m, W2m, b2m, W1n, W2n, b2n, b1m); break;
          case 1: stage_kernel<1><<<SBLK, STHR>>>(it, sub, outrow, pb, t, W1m, W2m, b2m, W1n, W2n, b2n, b1m); break;
          case 2: stage_kernel<2><<<SBLK, STHR>>>(it, sub, outrow, pb, t, W1m, W2m, b2m, W1n, W2n, b2n, b1m); break;
          case 3: stage_kernel<3><<<SBLK, STHR>>>(it, sub, outrow, pb, t, W1m, W2m, b2m, W1n, W2n, b2n, b1m); break;
          case 4: stage_kernel<4><<<SBLK, STHR>>>(it, sub, outrow, pb, t, W1m, W2m, b2m, W1n, W2n, b2n, b1m); break;
          case 5: stage_kernel<5><<<SBLK, STHR>>>(it, sub, outrow, pb, t, W1m, W2m, b2m, W1n, W2n, b2n, b1m); break;
        }
        L++;
      }
    }
  }

  gather_out_kernel<<<(TOUT * NF + 255) / 256, 256>>>(mask_idx, out);
}

// round 7
// speedup vs baseline: 1.8574x; 1.8574x over previous
#include <cuda_runtime.h>
#include <cuda_fp16.h>

#define NN 50000
#define FF 16
#define EE 800000
#define HH 64
#define TOUT 10
#define NF (NN*FF)
#define NBIN 1024
#define STHR 512
#define BW (STHR/32)            // 16 warps per block
#define SBLK ((NN + BW - 1)/BW) // 3125 blocks, warp per node

// ---------------- device state ----------------
__device__ float   g_x0[NF];
__device__ float   g_xi[NF];
__device__ float   g_k[6][NF];
__device__ __half2 g_uv[2][NN*32];   // packed u: (.x=ch lane, .y=ch lane+32), double-buffered
__device__ float   g_v[NN*HH];
__device__ float   g_augproj[NN*HH];
__device__ float   g_ys[TOUT*NF];
__device__ int     g_deg[NN];
__device__ int     g_rowptr[NN+1];
__device__ int     g_wptr[NN];
__device__ int     g_src_sorted[EE];
__device__ float4  g_ea_sorted[EE];
__device__ int     g_dbin[NBIN];
__device__ int     g_dwptr[NBIN];
__device__ int     g_nodes_sorted[NN];

// DOPRI5 coefficients. Row 0 unused, rows 1..5 = A[0..4], row 6 = B.
__constant__ float c_coef[7][6] = {
  {0.f,0.f,0.f,0.f,0.f,0.f},
  {(float)(0.2), 0.f,0.f,0.f,0.f,0.f},
  {(float)(3.0/40.0), (float)(9.0/40.0), 0.f,0.f,0.f,0.f},
  {(float)(44.0/45.0), (float)(-56.0/15.0), (float)(32.0/9.0), 0.f,0.f,0.f},
  {(float)(19372.0/6561.0), (float)(-25360.0/2187.0), (float)(64448.0/6561.0), (float)(-212.0/729.0), 0.f,0.f},
  {(float)(9017.0/3168.0), (float)(-355.0/33.0), (float)(46732.0/5247.0), (float)(49.0/176.0), (float)(-5103.0/18656.0), 0.f},
  {(float)(35.0/384.0), 0.f, (float)(500.0/1113.0), (float)(125.0/192.0), (float)(-2187.0/6784.0), (float)(11.0/84.0)}
};
__constant__ float c_C[6] = {0.f, 0.2f, 0.3f, 0.8f, (float)(8.0/9.0), 1.f};

__device__ __forceinline__ float tanha(float x) {
  float r;
  asm("tanh.approx.f32 %0, %1;" : "=f"(r) : "f"(x));
  return r;
}

// ---------------- setup kernels ----------------

// launch 0: initial state + zeroing of histograms
__global__ __launch_bounds__(256) void init_kernel(
    const float* __restrict__ xh,
    const float* __restrict__ W1m, const float* __restrict__ b1m)
{
  __shared__ float sW[32 * 64];
  __shared__ float sb[64];
  __shared__ float sxi[8][16];
  int tid = threadIdx.x;
  int gid = blockIdx.x * 256 + tid;
  if (gid < NN) g_deg[gid] = 0;
  if (gid < NBIN) g_dbin[gid] = 0;
  #pragma unroll
  for (int i = tid; i < 512; i += 256) ((float4*)sW)[i] = ((const float4*)W1m)[i];
  if (tid < 16) ((float4*)sb)[tid] = ((const float4*)b1m)[tid];
  int w = tid >> 5, lane = tid & 31;
  int n = blockIdx.x * 8 + w;
  if (n < NN) {
    if (lane < 16) {
      int idx = n * 16 + lane;
      float xv = xh[9 * NF + idx];
      g_x0[idx] = xv;
      g_xi[idx] = xv;
      sxi[w][lane] = xv;
    }
  }
  __syncthreads();
  if (n >= NN) return;
  float u0 = 0.f, u1 = 0.f;
  float v0 = sb[lane], v1 = sb[32 + lane];
  #pragma unroll
  for (int i = 0; i < 16; i++) {
    float xv = sxi[w][i];
    u0 += xv * sW[i * 64 + lane];
    u1 += xv * sW[i * 64 + 32 + lane];
    v0 += xv * sW[(16 + i) * 64 + lane];
    v1 += xv * sW[(16 + i) * 64 + 32 + lane];
  }
  g_uv[0][n * 32 + lane] = __floats2half2_rn(u0, u1);
  g_v[n * 64 + lane] = v0;
  g_v[n * 64 + 32 + lane] = v1;
}

// launch 1: aug features projected through W1n rows [32,208) with b1n folded in
__global__ __launch_bounds__(256) void augproj_kernel(
    const float* __restrict__ xh, const float* __restrict__ xm,
    const float* __restrict__ W1n, const float* __restrict__ b1n)
{
  __shared__ float saug[4][176];
  int tid = threadIdx.x;
  int ln = tid >> 6;
  int ch = tid & 63;
  int n = blockIdx.x * 4 + ln;
  if (ch < 16) {
    int f = ch;
    float xs[10], ms[10];
    float sm = 0.f, cm = 0.f;
    #pragma unroll
    for (int tt = 0; tt < 10; tt++) {
      xs[tt] = xh[(tt * NN + n) * FF + f];
      ms[tt] = xm[tt * NN + n];
      sm += xs[tt] * ms[tt];
      cm += ms[tt];
    }
    float cnt = fmaxf(cm, 1.0f);
    float mean = sm / cnt;
    float var = 0.f;
    #pragma unroll
    for (int tt = 0; tt < 10; tt++) { float d = xs[tt] - mean; var += d * d * ms[tt]; }
    var /= cnt;
    #pragma unroll
    for (int tt = 0; tt < 9; tt++)
      saug[ln][tt * 16 + f] = (xs[tt + 1] - xs[tt]) * (ms[tt + 1] * ms[tt]);
    saug[ln][144 + f] = mean;
    saug[ln][160 + f] = var;
  }
  __syncthreads();
  float acc = b1n[ch];
  #pragma unroll 8
  for (int r = 0; r < 176; r++)
    acc += saug[ln][r] * W1n[(32 + r) * 64 + ch];
  g_augproj[n * 64 + ch] = acc;
}

// launch 2: degree histogram
__global__ __launch_bounds__(256) void hist_kernel(const int* __restrict__ ei) {
  int e = blockIdx.x * 256 + threadIdx.x;
  if (e < EE) atomicAdd(&g_deg[ei[EE + e]], 1);
}

// launch 3: rowptr scan + degree-bin count + bin scan (single block)
__global__ __launch_bounds__(1024) void scan_kernel() {
  __shared__ int wsum[32];
  int tid = threadIdx.x, lane = tid & 31, wid = tid >> 5;
  int carry = 0;
  for (int base = 0; base < NN; base += 1024) {
    int i = base + tid;
    int v = (i < NN) ? g_deg[i] : 0;
    int x = v;
    #pragma unroll
    for (int o = 1; o < 32; o <<= 1) { int y = __shfl_up_sync(0xffffffffu, x, o); if (lane >= o) x += y; }
    if (lane == 31) wsum[wid] = x;
    __syncthreads();
    if (wid == 0) {
      int s = wsum[lane];
      #pragma unroll
      for (int o = 1; o < 32; o <<= 1) { int y = __shfl_up_sync(0xffffffffu, s, o); if (lane >= o) s += y; }
      wsum[lane] = s;
    }
    __syncthreads();
    int incl = x + carry + (wid > 0 ? wsum[wid - 1] : 0);
    if (i < NN) { g_rowptr[i + 1] = incl; g_wptr[i] = incl - v; }
    carry += wsum[31];
    __syncthreads();
  }
  if (tid == 0) g_rowptr[0] = 0;
  __syncthreads();
  // degree bins (descending order)
  for (int n = tid; n < NN; n += 1024) {
    int d = g_deg[n]; if (d > NBIN - 1) d = NBIN - 1;
    atomicAdd(&g_dbin[(NBIN - 1) - d], 1);
  }
  __syncthreads();
  // bin exclusive scan
  {
    int v = __ldcg(&g_dbin[tid]);
    int x = v;
    #pragma unroll
    for (int o = 1; o < 32; o <<= 1) { int y = __shfl_up_sync(0xffffffffu, x, o); if (lane >= o) x += y; }
    if (lane == 31) wsum[wid] = x;
    __syncthreads();
    if (wid == 0) {
      int s = wsum[lane];
      #pragma unroll
      for (int o = 1; o < 32; o <<= 1) { int y = __shfl_up_sync(0xffffffffu, s, o); if (lane >= o) s += y; }
      wsum[lane] = s;
    }
    __syncthreads();
    int incl = x + (wid > 0 ? wsum[wid - 1] : 0);
    g_dwptr[tid] = incl - v;
  }
}

// launch 4: edge scatter into CSR + node scatter into degree-sorted order
__global__ __launch_bounds__(256) void scatter_kernel(
    const int* __restrict__ ei, const float* __restrict__ ea)
{
  int e = blockIdx.x * 256 + threadIdx.x;
  if (e < EE) {
    int d = ei[EE + e];
    int pos = atomicAdd(&g_wptr[d], 1);
    g_src_sorted[pos] = ei[e];
    g_ea_sorted[pos] = ((const float4*)ea)[e];
  }
  if (e < NN) {
    int dd = g_deg[e]; if (dd > NBIN - 1) dd = NBIN - 1;
    int pos = atomicAdd(&g_dwptr[(NBIN - 1) - dd], 1);
    g_nodes_sorted[pos] = e;
  }
}

// ---------------- fused per-stage kernel (R4 structure, degree-sorted warp-per-node) ----------------
template<int S>
__global__ __launch_bounds__(STHR) void stage_kernel(
    int it, int sub, int outrow, int pb,
    const float* __restrict__ t,
    const float* __restrict__ W1m, const float* __restrict__ W2m,
    const float* __restrict__ b2m, const float* __restrict__ W1n,
    const float* __restrict__ W2n, const float* __restrict__ b2n,
    const float* __restrict__ b1m)
{
  __shared__ float sWea[4 * 64];
  __shared__ float sW2m[64 * 16];
  __shared__ float sW1nx[16 * 64];
  __shared__ float sW1na[16 * 64];
  __shared__ float sW2n[64 * 16];
  __shared__ float sW1m[32 * 64];
  __shared__ float swt[64];
  __shared__ float sb1m[64];
  __shared__ float sb2m[16], sb2n[16];
  __shared__ float sbuf[BW][64];
  __shared__ float sxi[BW][16];
  __shared__ float sagg[BW][16];
  __shared__ float sxin[BW][16];

  int tid = threadIdx.x;
  // stage weights (vectorized, one-shot)
  if (tid < 64)  ((float4*)sWea)[tid] = ((const float4*)(W1m + 32 * 64))[tid];
  for (int i = tid; i < 256; i += STHR) {
    ((float4*)sW2m)[i]  = ((const float4*)W2m)[i];
    ((float4*)sW1nx)[i] = ((const float4*)W1n)[i];
    ((float4*)sW1na)[i] = ((const float4*)(W1n + 1024))[i];
    ((float4*)sW2n)[i]  = ((const float4*)W2n)[i];
  }
  for (int i = tid; i < 512; i += STHR) ((float4*)sW1m)[i] = ((const float4*)W1m)[i];
  if (tid < 16) ((float4*)swt)[tid]  = ((const float4*)(W1n + 208 * 64))[tid];
  if (tid >= 16 && tid < 32) ((float4*)sb1m)[tid - 16] = ((const float4*)b1m)[tid - 16];
  if (tid >= 32 && tid < 36) ((float4*)sb2m)[tid - 32] = ((const float4*)b2m)[tid - 32];
  if (tid >= 36 && tid < 40) ((float4*)sb2n)[tid - 36] = ((const float4*)b2n)[tid - 36];

  int w = tid >> 5, lane = tid & 31;
  int n = g_nodes_sorted[blockIdx.x * BW + w];   // degree-sorted: warps in a block have ~equal degree
  if (lane < 16) sxi[w][lane] = g_xi[n * 16 + lane];
  __syncthreads();

  float tA = __ldg(t + it), tB = __ldg(t + it + 1);
  float dti = (tB - tA) * 0.25f;
  float ti = tA + (float)sub * dti + c_C[S] * dti;
  constexpr int krow = (S < 5) ? S + 1 : 6;

  const unsigned* __restrict__ U = (const unsigned*)&g_uv[pb][0];
  float v0 = g_v[n * 64 + lane];
  float v1 = g_v[n * 64 + 32 + lane];
  float wx0 = sWea[lane],        wx1 = sWea[32 + lane];
  float wy0 = sWea[64 + lane],   wy1 = sWea[96 + lane];
  float wz0 = sWea[128 + lane],  wz1 = sWea[160 + lane];
  float ww0 = sWea[192 + lane],  ww1 = sWea[224 + lane];

  float acc0 = 0.f, acc1 = 0.f;
  int beg = g_rowptr[n], end = g_rowptr[n + 1];

  // 3-slot software pipeline (prefetch depth 2)
  float4 eaA = make_float4(0.f,0.f,0.f,0.f), eaB = eaA;
  unsigned uhA = 0u, uhB = 0u;
  if (beg < end) {
    int s0 = __ldg(g_src_sorted + beg);
    eaA = __ldg(g_ea_sorted + beg);
    uhA = __ldg(U + s0 * 32 + lane);
  }
  if (beg + 1 < end) {
    int s1 = __ldg(g_src_sorted + beg + 1);
    eaB = __ldg(g_ea_sorted + beg + 1);
    uhB = __ldg(U + s1 * 32 + lane);
  }
  for (int e = beg; e < end; e++) {
    float4 ea = eaA; unsigned uh = uhA;
    eaA = eaB; uhA = uhB;
    if (e + 2 < end) {
      int sn = __ldg(g_src_sorted + e + 2);
      eaB = __ldg(g_ea_sorted + e + 2);
      uhB = __ldg(U + sn * 32 + lane);
    }
    __half2 h2 = *reinterpret_cast<__half2*>(&uh);
    float2 uf = __half22float2(h2);
    float a0 = uf.x + v0;
    float a1 = uf.y + v1;
    a0 += ea.x * wx0 + ea.y * wy0 + ea.z * wz0 + ea.w * ww0;
    a1 += ea.x * wx1 + ea.y * wy1 + ea.z * wz1 + ea.w * ww1;
    acc0 += tanha(a0);
    acc1 += tanha(a1);
  }

  // agg16 = hsum @ W2m + deg*b2m  (scalar stride-16 LDS: conflict-free)
  sbuf[w][lane] = acc0;
  sbuf[w][32 + lane] = acc1;
  __syncwarp();
  int j = lane & 15;
  int cbase = (lane < 16) ? 0 : 32;
  float p = 0.f;
  #pragma unroll
  for (int c = 0; c < 32; c++) p += sbuf[w][cbase + c] * sW2m[(cbase + c) * 16 + j];
  p += __shfl_xor_sync(0xffffffffu, p, 16);
  float degf = (float)(end - beg);
  if (lane < 16) sagg[w][lane] = p + degf * sb2m[j];
  __syncwarp();

  // hidden = xi@W1n_x + agg@W1n_agg + aug_proj + ti*wt
  float h0 = g_augproj[n * 64 + lane]      + ti * swt[lane];
  float h1 = g_augproj[n * 64 + 32 + lane] + ti * swt[32 + lane];
  #pragma unroll
  for (int i = 0; i < 16; i++) {
    float xv = sxi[w][i], av = sagg[w][i];
    h0 += xv * sW1nx[i * 64 + lane]      + av * sW1na[i * 64 + lane];
    h1 += xv * sW1nx[i * 64 + 32 + lane] + av * sW1na[i * 64 + 32 + lane];
  }
  __syncwarp();
  sbuf[w][lane] = tanha(h0);
  sbuf[w][32 + lane] = tanha(h1);
  __syncwarp();

  float o = 0.f;
  #pragma unroll
  for (int c = 0; c < 32; c++) o += sbuf[w][cbase + c] * sW2n[(cbase + c) * 16 + j];
  o += __shfl_xor_sync(0xffffffffu, o, 16);
  float kval = o + sb2n[j];

  // epilogue: k store, xi_{S+1} combine, u/v projection into buffer pb^1
  if (lane < 16) {
    int idx = n * 16 + j;
    g_k[S][idx] = kval;
    float acc = c_coef[krow][S] * kval;
    #pragma unroll
    for (int jj = 0; jj < S; jj++) acc += c_coef[krow][jj] * g_k[jj][idx];
    float xv = g_x0[idx] + dti * acc;
    if (S == 5) {
      g_x0[idx] = xv;
      if (outrow >= 0) g_ys[outrow * NF + idx] = xv;
    }
    g_xi[idx] = xv;
    sxin[w][j] = xv;
  }
  __syncwarp();

  float u0 = 0.f, u1 = 0.f;
  float nv0 = sb1m[lane], nv1 = sb1m[32 + lane];
  #pragma unroll
  for (int i = 0; i < 16; i++) {
    float xv = sxin[w][i];
    u0  += xv * sW1m[i * 64 + lane];
    u1  += xv * sW1m[i * 64 + 32 + lane];
    nv0 += xv * sW1m[(16 + i) * 64 + lane];
    nv1 += xv * sW1m[(16 + i) * 64 + 32 + lane];
  }
  g_uv[pb ^ 1][n * 32 + lane] = __floats2half2_rn(u0, u1);
  g_v[n * 64 + lane] = nv0;
  g_v[n * 64 + 32 + lane] = nv1;
}

__global__ __launch_bounds__(256) void gather_out_kernel(
    const int* __restrict__ mask_idx, float* __restrict__ out)
{
  int idx = blockIdx.x * 256 + threadIdx.x;
  if (idx < TOUT * NF) {
    int row = idx / NF;
    int rem = idx - row * NF;
    out[idx] = g_ys[mask_idx[row] * NF + rem];
  }
}

// ---------------- launcher ----------------
extern "C" void kernel_launch(void* const* d_in, const int* in_sizes, int n_in,
                              void* d_out, int out_size)
{
  const float* x_hist   = (const float*)d_in[0];
  const float* x_mask   = (const float*)d_in[1];
  const int*   ei       = (const int*)d_in[2];
  const float* ea       = (const float*)d_in[3];
  const float* t        = (const float*)d_in[4];
  const int*   mask_idx = (const int*)d_in[5];
  const float* W1m = (const float*)d_in[6];
  const float* b1m = (const float*)d_in[7];
  const float* W2m = (const float*)d_in[8];
  const float* b2m = (const float*)d_in[9];
  const float* W1n = (const float*)d_in[10];
  const float* b1n = (const float*)d_in[11];
  const float* W2n = (const float*)d_in[12];
  const float* b2n = (const float*)d_in[13];
  float* out = (float*)d_out;

  init_kernel<<<(NN + 7) / 8, 256>>>(x_hist, W1m, b1m);
  augproj_kernel<<<NN / 4, 256>>>(x_hist, x_mask, W1n, b1n);
  hist_kernel<<<(EE + 255) / 256, 256>>>(ei);
  scan_kernel<<<1, 1024>>>();
  scatter_kernel<<<(EE + 255) / 256, 256>>>(ei, ea);

  int L = 0;
  for (int it = 0; it < TOUT; it++) {
    for (int sub = 0; sub < 4; sub++) {
      for (int s = 0; s < 6; s++) {
        int outrow = (s == 5 && sub == 3) ? it : -1;
        int pb = L & 1;
        switch (s) {
          case 0: stage_kernel<0><<<SBLK, STHR>>>(it, sub, outrow, pb, t, W1m, W2m, b2m, W1n, W2n, b2n, b1m); break;
          case 1: stage_kernel<1><<<SBLK, STHR>>>(it, sub, outrow, pb, t, W1m, W2m, b2m, W1n, W2n, b2n, b1m); break;
          case 2: stage_kernel<2><<<SBLK, STHR>>>(it, sub, outrow, pb, t, W1m, W2m, b2m, W1n, W2n, b2n, b1m); break;
          case 3: stage_kernel<3><<<SBLK, STHR>>>(it, sub, outrow, pb, t, W1m, W2m, b2m, W1n, W2n, b2n, b1m); break;
          case 4: stage_kernel<4><<<SBLK, STHR>>>(it, sub, outrow, pb, t, W1m, W2m, b2m, W1n, W2n, b2n, b1m); break;
          case 5: stage_kernel<5><<<SBLK, STHR>>>(it, sub, outrow, pb, t, W1m, W2m, b2m, W1n, W2n, b2n, b1m); break;
        }
        L++;
      }
    }
  }

  gather_out_kernel<<<(TOUT * NF + 255) / 256, 256>>>(mask_idx, out);
}